// round 4
// baseline (speedup 1.0000x reference)
#include <cuda_runtime.h>
#include <cstdint>

#define SDIM 16
#define HDIM 128
#define HH 96
#define WW 96
#define NB 8
#define PLANE (HH * WW)            // 9216
#define FRAME (NB * SDIM * PLANE)  // 1179648

// ping-pong scratch: pre-gating updated state and alive_pre planes
__device__ float g_mid[2][FRAME];
__device__ float g_pre[2][NB * PLANE];

// ---------------------------------------------------------------------------
// Threefry-2x32 (JAX 20-round schedule), partitionable scheme
// ---------------------------------------------------------------------------
__host__ __device__ __forceinline__ void threefry2x32(
    uint32_t k0, uint32_t k1, uint32_t x0, uint32_t x1,
    uint32_t &o0, uint32_t &o1)
{
  uint32_t ks2 = k0 ^ k1 ^ 0x1BD11BDAu;
  x0 += k0; x1 += k1;
#define TFR(r) { x0 += x1; x1 = (x1 << (r)) | (x1 >> (32 - (r))); x1 ^= x0; }
  TFR(13) TFR(15) TFR(26) TFR(6)
  x0 += k1; x1 += ks2 + 1u;
  TFR(17) TFR(29) TFR(16) TFR(24)
  x0 += ks2; x1 += k0 + 2u;
  TFR(13) TFR(15) TFR(26) TFR(6)
  x0 += k0; x1 += k1 + 3u;
  TFR(17) TFR(29) TFR(16) TFR(24)
  x0 += k1; x1 += ks2 + 4u;
  TFR(13) TFR(15) TFR(26) TFR(6)
  x0 += ks2; x1 += k0 + 5u;
#undef TFR
  o0 = x0; o1 = x1;
}

// ---------------------------------------------------------------------------
// packed f32x2 helpers (Blackwell FFMA2)
// ---------------------------------------------------------------------------
typedef unsigned long long u64;

__device__ __forceinline__ void ffma2(u64 &acc, u64 a, u64 b) {
  asm("fma.rn.f32x2 %0, %1, %2, %0;" : "+l"(acc) : "l"(a), "l"(b));
}
__device__ __forceinline__ u64 pk(float lo, float hi) {
  u64 r; asm("mov.b64 %0, {%1, %2};" : "=l"(r) : "f"(lo), "f"(hi)); return r;
}
__device__ __forceinline__ float2 unpk(u64 v) {
  float2 r; asm("mov.b64 {%0, %1}, %2;" : "=f"(r.x), "=f"(r.y) : "l"(v)); return r;
}

// ---------------------------------------------------------------------------
// stepA (fused, 2 pixels/thread, software-pipelined weight loads)
// Block: 128 threads (16 x 8); thread handles tile rows ty and ty+8.
// ---------------------------------------------------------------------------
#define XS_FLOATS (SDIM * 18 * 18)   // 5184
#define W2_FLOATS (HDIM * 48)        // 6144
#define W3_FLOATS (SDIM * HDIM)      // 2048 (stored transposed: [o][c])
#define MIDA_FLOATS 400              // 20x20 mid-alpha halo
#define PREB_FLOATS 324              // 18x18 alive_pre
#define GA_FLOATS 324                // 18x18 gate
#define SMEM_FLOATS (XS_FLOATS + W2_FLOATS + W3_FLOATS + MIDA_FLOATS + PREB_FLOATS + GA_FLOATS)
#define SMEM_BYTES (SMEM_FLOATS * 4)
#define NTHR 128

extern "C" __global__ void __launch_bounds__(NTHR)
stepA(const float* __restrict__ x0in,
      const float* __restrict__ w2,
      const float* __restrict__ w3,
      float* __restrict__ frame_prev,   // out + (t-1)*FRAME (valid for t>0)
      int t, uint32_t k0, uint32_t k1)
{
  extern __shared__ float sm[];
  float* xs   = sm;                          // [16][18][18] gated x_t tile
  float* w2s  = xs + XS_FLOATS;              // [128][48]
  float* w3T  = w2s + W2_FLOATS;             // [128][16]  (transposed w3)
  float* midA = w3T + W3_FLOATS;             // [20][20]
  float* preb = midA + MIDA_FLOATS;          // [18][18]
  float* ga   = preb + PREB_FLOATS;          // [18][18]

  const int tx = threadIdx.x, ty = threadIdx.y;   // ty in [0,8)
  const int tid = ty * 16 + tx;
  const int b  = blockIdx.z;
  const int bh = blockIdx.y * 16;
  const int bw = blockIdx.x * 16;
  const int wb = t & 1;          // write buffer
  const int rb = 1 - wb;         // read buffer (mid_{t-1})

  // ---- RNG masks first: long independent ALU chains overlap tile loads ----
  uint32_t maskA = 0, maskB = 0;
  {
    const uint32_t baseA = (uint32_t)b * SDIM * PLANE
                         + (uint32_t)((bh + ty) * WW + (bw + tx));
    const uint32_t baseB = baseA + 8u * WW;
#pragma unroll 4
    for (int c = 0; c < 16; c++) {
      uint32_t o0, o1;
      threefry2x32(k0, k1, 0u, baseA + (uint32_t)c * PLANE, o0, o1);
      if (((o0 ^ o1) >> 9) > 0x400000u) maskA |= (1u << c);
      threefry2x32(k0, k1, 0u, baseB + (uint32_t)c * PLANE, o0, o1);
      if (((o0 ^ o1) >> 9) > 0x400000u) maskB |= (1u << c);
    }
  }

  // ---- cooperative loads: w2 (vectorized), w3 (transposed), halos ----
  {
    const float4* g2 = (const float4*)w2;
    float4* s2 = (float4*)w2s;
#pragma unroll
    for (int i = 0; i < 12; i++) s2[tid + i * NTHR] = g2[tid + i * NTHR];  // 1536
    // w3 [16][128] -> w3T [128][16]
#pragma unroll
    for (int i = 0; i < 16; i++) {
      int idx = tid + i * NTHR;            // idx = c*128 + o
      int c = idx >> 7, o = idx & 127;
      w3T[o * 16 + c] = w3[idx];
    }
  }
  if (t > 0) {
    const float* aplane = g_mid[rb] + ((size_t)b * SDIM + 3) * PLANE;
    for (int i = tid; i < MIDA_FLOATS; i += NTHR) {
      int rr = i / 20, qq = i - rr * 20;
      int gh = bh - 2 + rr, gw = bw - 2 + qq;
      midA[i] = ((unsigned)gh < HH && (unsigned)gw < WW)
                ? aplane[gh * WW + gw] : -1e30f;
    }
    const float* prer = g_pre[rb] + (size_t)b * PLANE;
    for (int i = tid; i < PREB_FLOATS; i += NTHR) {
      int rr = i / 18, qq = i - rr * 18;
      int gh = bh - 1 + rr, gw = bw - 1 + qq;
      preb[i] = ((unsigned)gh < HH && (unsigned)gw < WW)
                ? prer[gh * WW + gw] : 0.f;
    }
  }
  __syncthreads();

  // ---- gate = alive_pre & (maxpool3(mid alpha) > 0.1) on the 18x18 ring ----
  if (t > 0) {
    for (int i = tid; i < GA_FLOATS; i += NTHR) {
      int rr = i / 18, qq = i - rr * 18;
      float m = -1e30f;
#pragma unroll
      for (int dr = 0; dr < 3; dr++)
#pragma unroll
        for (int dq = 0; dq < 3; dq++)
          m = fmaxf(m, midA[(rr + dr) * 20 + qq + dq]);
      ga[i] = (preb[i] != 0.f && m > 0.1f) ? 1.f : 0.f;
    }
  }
  __syncthreads();

  // ---- build x_t tile (gated); interior also written as frame t-1 ----
  const float* srcb = (t == 0)
      ? (x0in + (size_t)b * SDIM * PLANE)
      : (g_mid[rb] + (size_t)b * SDIM * PLANE);
  for (int i = tid; i < XS_FLOATS; i += NTHR) {
    int c = i / 324;
    int rem = i - c * 324;
    int r = rem / 18, q = rem - r * 18;
    int gh = bh - 1 + r, gw = bw - 1 + q;
    float v = 0.f;
    if ((unsigned)gh < HH && (unsigned)gw < WW) {
      size_t gi = (size_t)c * PLANE + gh * WW + gw;
      v = srcb[gi];
      if (t > 0) {
        v *= ga[rem];
        if ((unsigned)(r - 1) < 16u && (unsigned)(q - 1) < 16u)
          frame_prev[(size_t)b * SDIM * PLANE + gi] = v;
      }
    }
    xs[i] = v;
  }
  __syncthreads();

  // ---- alive_pre for this step (from gated x_t alpha), both pixels ----
  const uint32_t pixA = (uint32_t)((bh + ty) * WW + (bw + tx));
  const uint32_t pixB = pixA + 8u * WW;
  {
    const float* pa = xs + 3 * 324;
    float mA = -1e30f, mB = -1e30f;
#pragma unroll
    for (int dr = 0; dr < 3; dr++)
#pragma unroll
      for (int dq = 0; dq < 3; dq++) {
        mA = fmaxf(mA, pa[(ty + dr) * 18 + tx + dq]);
        mB = fmaxf(mB, pa[(ty + 8 + dr) * 18 + tx + dq]);
      }
    g_pre[wb][(size_t)b * PLANE + pixA] = (mA > 0.1f) ? 1.f : 0.f;
    g_pre[wb][(size_t)b * PLANE + pixB] = (mB > 0.1f) ? 1.f : 0.f;
  }

  // ---- perception for both pixels ----
  u64 YA[24], YB[24];
  {
    float y[48];
#pragma unroll
    for (int c = 0; c < SDIM; c++) {
      const float* p = xs + c * 324 + ty * 18 + tx;
      float a00 = p[0],  a01 = p[1],  a02 = p[2];
      float a10 = p[18], a11 = p[19], a12 = p[20];
      float a20 = p[36], a21 = p[37], a22 = p[38];
      y[3 * c]     = a11;
      y[3 * c + 1] = ((a02 - a00) + 2.f * (a12 - a10) + (a22 - a20)) * 0.125f;
      y[3 * c + 2] = ((a20 - a00) + 2.f * (a21 - a01) + (a22 - a02)) * 0.125f;
    }
#pragma unroll
    for (int i = 0; i < 24; i++) YA[i] = pk(y[2 * i], y[2 * i + 1]);
#pragma unroll
    for (int c = 0; c < SDIM; c++) {
      const float* p = xs + c * 324 + (ty + 8) * 18 + tx;
      float a00 = p[0],  a01 = p[1],  a02 = p[2];
      float a10 = p[18], a11 = p[19], a12 = p[20];
      float a20 = p[36], a21 = p[37], a22 = p[38];
      y[3 * c]     = a11;
      y[3 * c + 1] = ((a02 - a00) + 2.f * (a12 - a10) + (a22 - a20)) * 0.125f;
      y[3 * c + 2] = ((a20 - a00) + 2.f * (a21 - a01) + (a22 - a02)) * 0.125f;
    }
#pragma unroll
    for (int i = 0; i < 24; i++) YB[i] = pk(y[2 * i], y[2 * i + 1]);
  }

  // ---- fused matvecs; D packed over output-channel pairs ----
  u64 DA[8], DB[8];
#pragma unroll
  for (int j = 0; j < 8; j++) { DA[j] = 0ull; DB[j] = 0ull; }

#pragma unroll 1
  for (int o = 0; o < HDIM; o += 4) {
    const ulonglong2* r0 = (const ulonglong2*)(w2s + (o + 0) * 48);
    const ulonglong2* r1 = (const ulonglong2*)(w2s + (o + 1) * 48);
    const ulonglong2* r2 = (const ulonglong2*)(w2s + (o + 2) * 48);
    const ulonglong2* r3 = (const ulonglong2*)(w2s + (o + 3) * 48);
    u64 aA0 = 0ull, aA1 = 0ull, aA2 = 0ull, aA3 = 0ull;
    u64 aB0 = 0ull, aB1 = 0ull, aB2 = 0ull, aB3 = 0ull;

    // software pipeline: stage kq+1 loads while consuming kq
    ulonglong2 c0 = r0[0], c1 = r1[0], c2 = r2[0], c3 = r3[0];
#pragma unroll
    for (int kq = 0; kq < 12; kq++) {
      ulonglong2 n0, n1, n2, n3;
      if (kq < 11) { n0 = r0[kq + 1]; n1 = r1[kq + 1]; n2 = r2[kq + 1]; n3 = r3[kq + 1]; }
      u64 yAl = YA[2 * kq], yAh = YA[2 * kq + 1];
      u64 yBl = YB[2 * kq], yBh = YB[2 * kq + 1];
      ffma2(aA0, c0.x, yAl); ffma2(aA0, c0.y, yAh);
      ffma2(aB0, c0.x, yBl); ffma2(aB0, c0.y, yBh);
      ffma2(aA1, c1.x, yAl); ffma2(aA1, c1.y, yAh);
      ffma2(aB1, c1.x, yBl); ffma2(aB1, c1.y, yBh);
      ffma2(aA2, c2.x, yAl); ffma2(aA2, c2.y, yAh);
      ffma2(aB2, c2.x, yBl); ffma2(aB2, c2.y, yBh);
      ffma2(aA3, c3.x, yAl); ffma2(aA3, c3.y, yAh);
      ffma2(aB3, c3.x, yBl); ffma2(aB3, c3.y, yBh);
      if (kq < 11) { c0 = n0; c1 = n1; c2 = n2; c3 = n3; }
    }

    float2 fA0 = unpk(aA0), fA1 = unpk(aA1), fA2 = unpk(aA2), fA3 = unpk(aA3);
    float2 fB0 = unpk(aB0), fB1 = unpk(aB1), fB2 = unpk(aB2), fB3 = unpk(aB3);
    float hA[4], hB[4];
    hA[0] = fmaxf(fA0.x + fA0.y, 0.f); hA[1] = fmaxf(fA1.x + fA1.y, 0.f);
    hA[2] = fmaxf(fA2.x + fA2.y, 0.f); hA[3] = fmaxf(fA3.x + fA3.y, 0.f);
    hB[0] = fmaxf(fB0.x + fB0.y, 0.f); hB[1] = fmaxf(fB1.x + fB1.y, 0.f);
    hB[2] = fmaxf(fB2.x + fB2.y, 0.f); hB[3] = fmaxf(fB3.x + fB3.y, 0.f);

#pragma unroll
    for (int oo = 0; oo < 4; oo++) {
      const ulonglong2* wrow = (const ulonglong2*)(w3T + (o + oo) * 16);
      u64 sA = pk(hA[oo], hA[oo]);
      u64 sB = pk(hB[oo], hB[oo]);
#pragma unroll
      for (int j = 0; j < 4; j++) {
        ulonglong2 wp = wrow[j];
        ffma2(DA[2 * j],     wp.x, sA); ffma2(DA[2 * j + 1], wp.y, sA);
        ffma2(DB[2 * j],     wp.x, sB); ffma2(DB[2 * j + 1], wp.y, sB);
      }
    }
  }

  // ---- stochastic update, write mid_t for both pixels ----
  float* midw = g_mid[wb] + (size_t)b * SDIM * PLANE;
#pragma unroll
  for (int j = 0; j < 8; j++) {
    float2 dA = unpk(DA[j]);
    float2 dB = unpk(DB[j]);
    int c0i = 2 * j, c1i = 2 * j + 1;
    float vA0 = xs[c0i * 324 + (ty + 1) * 18 + (tx + 1)]
              + (((maskA >> c0i) & 1u) ? dA.x : 0.f);
    float vA1 = xs[c1i * 324 + (ty + 1) * 18 + (tx + 1)]
              + (((maskA >> c1i) & 1u) ? dA.y : 0.f);
    midw[(size_t)c0i * PLANE + pixA] = vA0;
    midw[(size_t)c1i * PLANE + pixA] = vA1;
    float vB0 = xs[c0i * 324 + (ty + 9) * 18 + (tx + 1)]
              + (((maskB >> c0i) & 1u) ? dB.x : 0.f);
    float vB1 = xs[c1i * 324 + (ty + 9) * 18 + (tx + 1)]
              + (((maskB >> c1i) & 1u) ? dB.y : 0.f);
    midw[(size_t)c0i * PLANE + pixB] = vB0;
    midw[(size_t)c1i * PLANE + pixB] = vB1;
  }
}

// ---------------------------------------------------------------------------
// stepC: gate and emit the final frame.
// ---------------------------------------------------------------------------
extern "C" __global__ void __launch_bounds__(256)
stepC(float* __restrict__ outf, int pb)
{
  int p = blockIdx.x * 256 + threadIdx.x;
  if (p >= NB * PLANE) return;
  int b = p / PLANE;
  int hw = p - b * PLANE;
  int h = hw / WW, w = hw - h * WW;

  const float* mida = g_mid[pb] + ((size_t)b * SDIM + 3) * PLANE;
  float m = -1e30f;
#pragma unroll
  for (int di = -1; di <= 1; di++) {
    int hh = h + di;
    if ((unsigned)hh >= HH) continue;
#pragma unroll
    for (int dj = -1; dj <= 1; dj++) {
      int wq = w + dj;
      if ((unsigned)wq >= WW) continue;
      m = fmaxf(m, mida[hh * WW + wq]);
    }
  }
  float gate = (g_pre[pb][p] != 0.f && m > 0.1f) ? 1.f : 0.f;

  size_t base = (size_t)b * SDIM * PLANE + (size_t)hw;
#pragma unroll
  for (int c = 0; c < 16; c++)
    outf[base + c * PLANE] = g_mid[pb][base + c * PLANE] * gate;
}

// ---------------------------------------------------------------------------
// kernel_launch
// ---------------------------------------------------------------------------
extern "C" void kernel_launch(void* const* d_in, const int* in_sizes, int n_in,
                              void* d_out, int out_size)
{
  const float* x0 = (const float*)d_in[0];
  const float* w2 = (const float*)d_in[3];
  const float* w3 = (const float*)d_in[4];
  float* out = (float*)d_out;

  const int nsteps = out_size / FRAME;

  cudaFuncSetAttribute(stepA, cudaFuncAttributeMaxDynamicSharedMemorySize, SMEM_BYTES);

  for (int t = 0; t < nsteps; t++) {
    uint32_t sk0, sk1;
    threefry2x32(0u, 42u, 0u, (uint32_t)t, sk0, sk1);   // key_t = fold(key42, t)
    float* fprev = out + (size_t)(t > 0 ? t - 1 : 0) * FRAME;
    stepA<<<dim3(6, 6, NB), dim3(16, 8), SMEM_BYTES>>>(x0, w2, w3, fprev, t, sk0, sk1);
  }
  stepC<<<(NB * PLANE + 255) / 256, 256>>>(out + (size_t)(nsteps - 1) * FRAME,
                                           (nsteps - 1) & 1);
}

// round 5
// speedup vs baseline: 1.0214x; 1.0214x over previous
#include <cuda_runtime.h>
#include <cstdint>

#define SDIM 16
#define HDIM 128
#define HH 96
#define WW 96
#define NB 8
#define PLANE (HH * WW)            // 9216
#define FRAME (NB * SDIM * PLANE)  // 1179648

// ping-pong scratch: pre-gating updated state and alive_pre planes
__device__ float g_mid[2][FRAME];
__device__ float g_pre[2][NB * PLANE];

// ---------------------------------------------------------------------------
// Threefry-2x32 (JAX 20-round schedule), partitionable scheme
// ---------------------------------------------------------------------------
__host__ __device__ __forceinline__ void threefry2x32(
    uint32_t k0, uint32_t k1, uint32_t x0, uint32_t x1,
    uint32_t &o0, uint32_t &o1)
{
  uint32_t ks2 = k0 ^ k1 ^ 0x1BD11BDAu;
  x0 += k0; x1 += k1;
#define TFR(r) { x0 += x1; x1 = (x1 << (r)) | (x1 >> (32 - (r))); x1 ^= x0; }
  TFR(13) TFR(15) TFR(26) TFR(6)
  x0 += k1; x1 += ks2 + 1u;
  TFR(17) TFR(29) TFR(16) TFR(24)
  x0 += ks2; x1 += k0 + 2u;
  TFR(13) TFR(15) TFR(26) TFR(6)
  x0 += k0; x1 += k1 + 3u;
  TFR(17) TFR(29) TFR(16) TFR(24)
  x0 += k1; x1 += ks2 + 4u;
  TFR(13) TFR(15) TFR(26) TFR(6)
  x0 += ks2; x1 += k0 + 5u;
#undef TFR
  o0 = x0; o1 = x1;
}

// ---------------------------------------------------------------------------
// packed f32x2 helpers (Blackwell FFMA2)
// ---------------------------------------------------------------------------
typedef unsigned long long u64;

__device__ __forceinline__ void ffma2(u64 &acc, u64 a, u64 b) {
  asm("fma.rn.f32x2 %0, %1, %2, %0;" : "+l"(acc) : "l"(a), "l"(b));
}
__device__ __forceinline__ u64 pk(float lo, float hi) {
  u64 r; asm("mov.b64 %0, {%1, %2};" : "=l"(r) : "f"(lo), "f"(hi)); return r;
}
__device__ __forceinline__ float2 unpk(u64 v) {
  float2 r; asm("mov.b64 {%0, %1}, %2;" : "=f"(r.x), "=f"(r.y) : "l"(v)); return r;
}

// ---------------------------------------------------------------------------
// stepA (fused, 2 pixels/thread, RNG interleaved into matvec, dead-warp skip)
// Block: 128 threads (16 x 8); thread handles tile rows ty and ty+8.
// ---------------------------------------------------------------------------
#define XS_FLOATS (SDIM * 18 * 18)   // 5184
#define W2_FLOATS (HDIM * 48)        // 6144
#define W3_FLOATS (SDIM * HDIM)      // 2048 (stored transposed: [o][c])
#define MIDA_FLOATS 400              // 20x20 mid-alpha halo
#define PREB_FLOATS 324              // 18x18 alive_pre
#define GA_FLOATS 324                // 18x18 gate
#define SMEM_FLOATS (XS_FLOATS + W2_FLOATS + W3_FLOATS + MIDA_FLOATS + PREB_FLOATS + GA_FLOATS)
#define SMEM_BYTES (SMEM_FLOATS * 4)
#define NTHR 128

extern "C" __global__ void __launch_bounds__(NTHR)
stepA(const float* __restrict__ x0in,
      const float* __restrict__ w2,
      const float* __restrict__ w3,
      float* __restrict__ frame_prev,   // out + (t-1)*FRAME (valid for t>0)
      int t, uint32_t k0, uint32_t k1)
{
  extern __shared__ float sm[];
  float* xs   = sm;                          // [16][18][18] gated x_t tile
  float* w2s  = xs + XS_FLOATS;              // [128][48]
  float* w3T  = w2s + W2_FLOATS;             // [128][16]  (transposed w3)
  float* midA = w3T + W3_FLOATS;             // [20][20]
  float* preb = midA + MIDA_FLOATS;          // [18][18]
  float* ga   = preb + PREB_FLOATS;          // [18][18]

  const int tx = threadIdx.x, ty = threadIdx.y;   // ty in [0,8)
  const int tid = ty * 16 + tx;
  const int b  = blockIdx.z;
  const int bh = blockIdx.y * 16;
  const int bw = blockIdx.x * 16;
  const int wb = t & 1;          // write buffer
  const int rb = 1 - wb;         // read buffer (mid_{t-1})

  // ---- cooperative loads: w2 (vectorized), w3 (transposed), halos ----
  {
    const float4* g2 = (const float4*)w2;
    float4* s2 = (float4*)w2s;
#pragma unroll
    for (int i = 0; i < 12; i++) s2[tid + i * NTHR] = g2[tid + i * NTHR];  // 1536
    // w3 [16][128] -> w3T [128][16]
#pragma unroll
    for (int i = 0; i < 16; i++) {
      int idx = tid + i * NTHR;            // idx = c*128 + o
      int c = idx >> 7, o = idx & 127;
      w3T[o * 16 + c] = w3[idx];
    }
  }
  if (t > 0) {
    const float* aplane = g_mid[rb] + ((size_t)b * SDIM + 3) * PLANE;
    for (int i = tid; i < MIDA_FLOATS; i += NTHR) {
      int rr = i / 20, qq = i - rr * 20;
      int gh = bh - 2 + rr, gw = bw - 2 + qq;
      midA[i] = ((unsigned)gh < HH && (unsigned)gw < WW)
                ? aplane[gh * WW + gw] : -1e30f;
    }
    const float* prer = g_pre[rb] + (size_t)b * PLANE;
    for (int i = tid; i < PREB_FLOATS; i += NTHR) {
      int rr = i / 18, qq = i - rr * 18;
      int gh = bh - 1 + rr, gw = bw - 1 + qq;
      preb[i] = ((unsigned)gh < HH && (unsigned)gw < WW)
                ? prer[gh * WW + gw] : 0.f;
    }
  }
  __syncthreads();

  // ---- gate = alive_pre & (maxpool3(mid alpha) > 0.1) on the 18x18 ring ----
  if (t > 0) {
    for (int i = tid; i < GA_FLOATS; i += NTHR) {
      int rr = i / 18, qq = i - rr * 18;
      float m = -1e30f;
#pragma unroll
      for (int dr = 0; dr < 3; dr++)
#pragma unroll
        for (int dq = 0; dq < 3; dq++)
          m = fmaxf(m, midA[(rr + dr) * 20 + qq + dq]);
      ga[i] = (preb[i] != 0.f && m > 0.1f) ? 1.f : 0.f;
    }
  }
  __syncthreads();

  // ---- build x_t tile (gated); interior also written as frame t-1 ----
  const float* srcb = (t == 0)
      ? (x0in + (size_t)b * SDIM * PLANE)
      : (g_mid[rb] + (size_t)b * SDIM * PLANE);
  for (int i = tid; i < XS_FLOATS; i += NTHR) {
    int c = i / 324;
    int rem = i - c * 324;
    int r = rem / 18, q = rem - r * 18;
    int gh = bh - 1 + r, gw = bw - 1 + q;
    float v = 0.f;
    if ((unsigned)gh < HH && (unsigned)gw < WW) {
      size_t gi = (size_t)c * PLANE + gh * WW + gw;
      v = srcb[gi];
      if (t > 0) {
        v *= ga[rem];
        if ((unsigned)(r - 1) < 16u && (unsigned)(q - 1) < 16u)
          frame_prev[(size_t)b * SDIM * PLANE + gi] = v;
      }
    }
    xs[i] = v;
  }
  __syncthreads();

  // ---- alive_pre for this step (from gated x_t alpha), both pixels ----
  const uint32_t pixA = (uint32_t)((bh + ty) * WW + (bw + tx));
  const uint32_t pixB = pixA + 8u * WW;
  {
    const float* pa = xs + 3 * 324;
    float mA = -1e30f, mB = -1e30f;
#pragma unroll
    for (int dr = 0; dr < 3; dr++)
#pragma unroll
      for (int dq = 0; dq < 3; dq++) {
        mA = fmaxf(mA, pa[(ty + dr) * 18 + tx + dq]);
        mB = fmaxf(mB, pa[(ty + 8 + dr) * 18 + tx + dq]);
      }
    g_pre[wb][(size_t)b * PLANE + pixA] = (mA > 0.1f) ? 1.f : 0.f;
    g_pre[wb][(size_t)b * PLANE + pixB] = (mB > 0.1f) ? 1.f : 0.f;
  }

  // ---- perception for both pixels; track liveness for dead-warp skip ----
  u64 YA[24], YB[24];
  uint32_t nzbits = 0;
  {
    float y[48];
#pragma unroll
    for (int c = 0; c < SDIM; c++) {
      const float* p = xs + c * 324 + ty * 18 + tx;
      float a00 = p[0],  a01 = p[1],  a02 = p[2];
      float a10 = p[18], a11 = p[19], a12 = p[20];
      float a20 = p[36], a21 = p[37], a22 = p[38];
      y[3 * c]     = a11;
      y[3 * c + 1] = ((a02 - a00) + 2.f * (a12 - a10) + (a22 - a20)) * 0.125f;
      y[3 * c + 2] = ((a20 - a00) + 2.f * (a21 - a01) + (a22 - a02)) * 0.125f;
      nzbits |= __float_as_uint(a00) | __float_as_uint(a01) | __float_as_uint(a02)
              | __float_as_uint(a10) | __float_as_uint(a11) | __float_as_uint(a12)
              | __float_as_uint(a20) | __float_as_uint(a21) | __float_as_uint(a22);
    }
#pragma unroll
    for (int i = 0; i < 24; i++) YA[i] = pk(y[2 * i], y[2 * i + 1]);
#pragma unroll
    for (int c = 0; c < SDIM; c++) {
      const float* p = xs + c * 324 + (ty + 8) * 18 + tx;
      float a00 = p[0],  a01 = p[1],  a02 = p[2];
      float a10 = p[18], a11 = p[19], a12 = p[20];
      float a20 = p[36], a21 = p[37], a22 = p[38];
      y[3 * c]     = a11;
      y[3 * c + 1] = ((a02 - a00) + 2.f * (a12 - a10) + (a22 - a20)) * 0.125f;
      y[3 * c + 2] = ((a20 - a00) + 2.f * (a21 - a01) + (a22 - a02)) * 0.125f;
      nzbits |= __float_as_uint(a00) | __float_as_uint(a01) | __float_as_uint(a02)
              | __float_as_uint(a10) | __float_as_uint(a11) | __float_as_uint(a12)
              | __float_as_uint(a20) | __float_as_uint(a21) | __float_as_uint(a22);
    }
#pragma unroll
    for (int i = 0; i < 24; i++) YB[i] = pk(y[2 * i], y[2 * i + 1]);
  }
  // warp is dead iff every lane's 3x3 inputs were (+/-)0 for all channels
  const bool warp_alive =
      (__ballot_sync(0xffffffffu, (nzbits & 0x7fffffffu) != 0u) != 0u);

  // ---- fused matvecs with RNG interleaved; D packed over channel pairs ----
  u64 DA[8], DB[8];
#pragma unroll
  for (int j = 0; j < 8; j++) { DA[j] = 0ull; DB[j] = 0ull; }
  uint32_t maskA = 0, maskB = 0;

  if (warp_alive) {
    const uint32_t baseA = (uint32_t)b * SDIM * PLANE + pixA;
    const uint32_t baseB = baseA + 8u * WW;

#pragma unroll 1
    for (int o = 0; o < HDIM; o += 4) {
      // one threefry per o-iteration: fills fma-pipe stall slots with alu work
      {
        int i = o >> 2;                      // 0..31
        uint32_t idx = (i < 16) ? (baseA + (uint32_t)i * PLANE)
                                : (baseB + (uint32_t)(i - 16) * PLANE);
        uint32_t o0r, o1r;
        threefry2x32(k0, k1, 0u, idx, o0r, o1r);
        uint32_t bit = (((o0r ^ o1r) >> 9) > 0x400000u) ? 1u : 0u;
        if (i < 16) maskA |= bit << i; else maskB |= bit << (i - 16);
      }

      const ulonglong2* r0 = (const ulonglong2*)(w2s + (o + 0) * 48);
      const ulonglong2* r1 = (const ulonglong2*)(w2s + (o + 1) * 48);
      const ulonglong2* r2 = (const ulonglong2*)(w2s + (o + 2) * 48);
      const ulonglong2* r3 = (const ulonglong2*)(w2s + (o + 3) * 48);
      u64 aA0 = 0ull, aA1 = 0ull, aA2 = 0ull, aA3 = 0ull;
      u64 aB0 = 0ull, aB1 = 0ull, aB2 = 0ull, aB3 = 0ull;
#pragma unroll
      for (int kq = 0; kq < 12; kq += 2) {
        // batch 8 LDS.128 (MLP) then 32 FFMA2
        ulonglong2 b00 = r0[kq], b01 = r0[kq + 1];
        ulonglong2 b10 = r1[kq], b11 = r1[kq + 1];
        ulonglong2 b20 = r2[kq], b21 = r2[kq + 1];
        ulonglong2 b30 = r3[kq], b31 = r3[kq + 1];
        u64 yA0 = YA[2 * kq],     yA1 = YA[2 * kq + 1];
        u64 yA2 = YA[2 * kq + 2], yA3 = YA[2 * kq + 3];
        u64 yB0 = YB[2 * kq],     yB1 = YB[2 * kq + 1];
        u64 yB2 = YB[2 * kq + 2], yB3 = YB[2 * kq + 3];
        ffma2(aA0, b00.x, yA0); ffma2(aA0, b00.y, yA1);
        ffma2(aB0, b00.x, yB0); ffma2(aB0, b00.y, yB1);
        ffma2(aA1, b10.x, yA0); ffma2(aA1, b10.y, yA1);
        ffma2(aB1, b10.x, yB0); ffma2(aB1, b10.y, yB1);
        ffma2(aA2, b20.x, yA0); ffma2(aA2, b20.y, yA1);
        ffma2(aB2, b20.x, yB0); ffma2(aB2, b20.y, yB1);
        ffma2(aA3, b30.x, yA0); ffma2(aA3, b30.y, yA1);
        ffma2(aB3, b30.x, yB0); ffma2(aB3, b30.y, yB1);
        ffma2(aA0, b01.x, yA2); ffma2(aA0, b01.y, yA3);
        ffma2(aB0, b01.x, yB2); ffma2(aB0, b01.y, yB3);
        ffma2(aA1, b11.x, yA2); ffma2(aA1, b11.y, yA3);
        ffma2(aB1, b11.x, yB2); ffma2(aB1, b11.y, yB3);
        ffma2(aA2, b21.x, yA2); ffma2(aA2, b21.y, yA3);
        ffma2(aB2, b21.x, yB2); ffma2(aB2, b21.y, yB3);
        ffma2(aA3, b31.x, yA2); ffma2(aA3, b31.y, yA3);
        ffma2(aB3, b31.x, yB2); ffma2(aB3, b31.y, yB3);
      }

      float2 fA0 = unpk(aA0), fA1 = unpk(aA1), fA2 = unpk(aA2), fA3 = unpk(aA3);
      float2 fB0 = unpk(aB0), fB1 = unpk(aB1), fB2 = unpk(aB2), fB3 = unpk(aB3);
      float hA[4], hB[4];
      hA[0] = fmaxf(fA0.x + fA0.y, 0.f); hA[1] = fmaxf(fA1.x + fA1.y, 0.f);
      hA[2] = fmaxf(fA2.x + fA2.y, 0.f); hA[3] = fmaxf(fA3.x + fA3.y, 0.f);
      hB[0] = fmaxf(fB0.x + fB0.y, 0.f); hB[1] = fmaxf(fB1.x + fB1.y, 0.f);
      hB[2] = fmaxf(fB2.x + fB2.y, 0.f); hB[3] = fmaxf(fB3.x + fB3.y, 0.f);

#pragma unroll
      for (int oo = 0; oo < 4; oo++) {
        const ulonglong2* wrow = (const ulonglong2*)(w3T + (o + oo) * 16);
        u64 sA = pk(hA[oo], hA[oo]);
        u64 sB = pk(hB[oo], hB[oo]);
#pragma unroll
        for (int j = 0; j < 4; j++) {
          ulonglong2 wp = wrow[j];
          ffma2(DA[2 * j],     wp.x, sA); ffma2(DA[2 * j + 1], wp.y, sA);
          ffma2(DB[2 * j],     wp.x, sB); ffma2(DB[2 * j + 1], wp.y, sB);
        }
      }
    }
  }

  // ---- stochastic update, write mid_t for both pixels ----
  float* midw = g_mid[wb] + (size_t)b * SDIM * PLANE;
#pragma unroll
  for (int j = 0; j < 8; j++) {
    float2 dA = unpk(DA[j]);
    float2 dB = unpk(DB[j]);
    int c0i = 2 * j, c1i = 2 * j + 1;
    float vA0 = xs[c0i * 324 + (ty + 1) * 18 + (tx + 1)]
              + (((maskA >> c0i) & 1u) ? dA.x : 0.f);
    float vA1 = xs[c1i * 324 + (ty + 1) * 18 + (tx + 1)]
              + (((maskA >> c1i) & 1u) ? dA.y : 0.f);
    midw[(size_t)c0i * PLANE + pixA] = vA0;
    midw[(size_t)c1i * PLANE + pixA] = vA1;
    float vB0 = xs[c0i * 324 + (ty + 9) * 18 + (tx + 1)]
              + (((maskB >> c0i) & 1u) ? dB.x : 0.f);
    float vB1 = xs[c1i * 324 + (ty + 9) * 18 + (tx + 1)]
              + (((maskB >> c1i) & 1u) ? dB.y : 0.f);
    midw[(size_t)c0i * PLANE + pixB] = vB0;
    midw[(size_t)c1i * PLANE + pixB] = vB1;
  }
}

// ---------------------------------------------------------------------------
// stepC: gate and emit the final frame.
// ---------------------------------------------------------------------------
extern "C" __global__ void __launch_bounds__(256)
stepC(float* __restrict__ outf, int pb)
{
  int p = blockIdx.x * 256 + threadIdx.x;
  if (p >= NB * PLANE) return;
  int b = p / PLANE;
  int hw = p - b * PLANE;
  int h = hw / WW, w = hw - h * WW;

  const float* mida = g_mid[pb] + ((size_t)b * SDIM + 3) * PLANE;
  float m = -1e30f;
#pragma unroll
  for (int di = -1; di <= 1; di++) {
    int hh = h + di;
    if ((unsigned)hh >= HH) continue;
#pragma unroll
    for (int dj = -1; dj <= 1; dj++) {
      int wq = w + dj;
      if ((unsigned)wq >= WW) continue;
      m = fmaxf(m, mida[hh * WW + wq]);
    }
  }
  float gate = (g_pre[pb][p] != 0.f && m > 0.1f) ? 1.f : 0.f;

  size_t base = (size_t)b * SDIM * PLANE + (size_t)hw;
#pragma unroll
  for (int c = 0; c < 16; c++)
    outf[base + c * PLANE] = g_mid[pb][base + c * PLANE] * gate;
}

// ---------------------------------------------------------------------------
// kernel_launch
// ---------------------------------------------------------------------------
extern "C" void kernel_launch(void* const* d_in, const int* in_sizes, int n_in,
                              void* d_out, int out_size)
{
  const float* x0 = (const float*)d_in[0];
  const float* w2 = (const float*)d_in[3];
  const float* w3 = (const float*)d_in[4];
  float* out = (float*)d_out;

  const int nsteps = out_size / FRAME;

  cudaFuncSetAttribute(stepA, cudaFuncAttributeMaxDynamicSharedMemorySize, SMEM_BYTES);

  for (int t = 0; t < nsteps; t++) {
    uint32_t sk0, sk1;
    threefry2x32(0u, 42u, 0u, (uint32_t)t, sk0, sk1);   // key_t = fold(key42, t)
    float* fprev = out + (size_t)(t > 0 ? t - 1 : 0) * FRAME;
    stepA<<<dim3(6, 6, NB), dim3(16, 8), SMEM_BYTES>>>(x0, w2, w3, fprev, t, sk0, sk1);
  }
  stepC<<<(NB * PLANE + 255) / 256, 256>>>(out + (size_t)(nsteps - 1) * FRAME,
                                           (nsteps - 1) & 1);
}

// round 10
// speedup vs baseline: 1.2250x; 1.1994x over previous
#include <cuda_runtime.h>
#include <cuda_bf16.h>
#include <cstdint>

#define SDIM 16
#define HDIM 128
#define HH 96
#define WW 96
#define NB 8
#define PLANE (HH * WW)            // 9216
#define FRAME (NB * SDIM * PLANE)  // 1179648

typedef unsigned long long u64;

// ping-pong scratch
__device__ float g_mid[2][FRAME];
__device__ float g_pre[2][NB * PLANE];
// weights pre-split (bf16x3) and pre-arranged in mma fragment layout
// w2frag[s(3)][kt(3)][nt(16)][lane(32)] : u64 = {b0, b1} of m16n8k16 B-frag
__device__ __align__(16) u64 g_w2frag[3 * 3 * 16 * 32];   // 36864 B
// w3frag[s(3)][kc(8)][nt(2)][lane(32)]
__device__ __align__(16) u64 g_w3frag[3 * 8 * 2 * 32];    // 12288 B

// ---------------------------------------------------------------------------
// Threefry-2x32 (JAX 20-round schedule), partitionable scheme
// ---------------------------------------------------------------------------
__host__ __device__ __forceinline__ void threefry2x32(
    uint32_t k0, uint32_t k1, uint32_t x0, uint32_t x1,
    uint32_t &o0, uint32_t &o1)
{
  uint32_t ks2 = k0 ^ k1 ^ 0x1BD11BDAu;
  x0 += k0; x1 += k1;
#define TFR(r) { x0 += x1; x1 = (x1 << (r)) | (x1 >> (32 - (r))); x1 ^= x0; }
  TFR(13) TFR(15) TFR(26) TFR(6)
  x0 += k1; x1 += ks2 + 1u;
  TFR(17) TFR(29) TFR(16) TFR(24)
  x0 += ks2; x1 += k0 + 2u;
  TFR(13) TFR(15) TFR(26) TFR(6)
  x0 += k0; x1 += k1 + 3u;
  TFR(17) TFR(29) TFR(16) TFR(24)
  x0 += k1; x1 += ks2 + 4u;
  TFR(13) TFR(15) TFR(26) TFR(6)
  x0 += ks2; x1 += k0 + 5u;
#undef TFR
  o0 = x0; o1 = x1;
}

// ---------------------------------------------------------------------------
// bf16 split helpers
// ---------------------------------------------------------------------------
__device__ __forceinline__ float bf16rt(float x, uint16_t &bits) {
  __nv_bfloat16 b = __float2bfloat16_rn(x);
  bits = __bfloat16_as_ushort(b);
  return __bfloat162float(b);
}
__device__ __forceinline__ void split3(float v, uint16_t &h, uint16_t &m, uint16_t &l) {
  float fh = bf16rt(v, h);
  float r = v - fh;
  float fm = bf16rt(r, m);
  bf16rt(r - fm, l);
}
__device__ __forceinline__ uint16_t splitbits(float v, int s) {
  uint16_t h, m, l;
  split3(v, h, m, l);
  return (s == 0) ? h : (s == 1) ? m : l;
}

// ---------------------------------------------------------------------------
// mma.sync m16n8k16 bf16 (portable ISA, compiles to fallback HMMA on sm_103)
// ---------------------------------------------------------------------------
__device__ __forceinline__ void mma_bf16(float* c, const uint32_t* a,
                                         uint32_t b0, uint32_t b1) {
  asm volatile(
      "mma.sync.aligned.m16n8k16.row.col.f32.bf16.bf16.f32 "
      "{%0,%1,%2,%3}, {%4,%5,%6,%7}, {%8,%9}, {%0,%1,%2,%3};"
      : "+f"(c[0]), "+f"(c[1]), "+f"(c[2]), "+f"(c[3])
      : "r"(a[0]), "r"(a[1]), "r"(a[2]), "r"(a[3]), "r"(b0), "r"(b1));
}

// ---------------------------------------------------------------------------
// prep: build fragment-layout split weights (runs once per launch, tiny)
// B-frag (m16n8k16, col): lane l (q=l&3, g=l>>2):
//   b0 = {B[k0][n], B[k0+1][n]}, b1 = {B[k0+8][n], B[k0+9][n]},
//   k0 = kt*16 + 2q, n = nt*8 + g
// ---------------------------------------------------------------------------
extern "C" __global__ void prep(const float* __restrict__ w2, const float* __restrict__ w3)
{
  int tid = threadIdx.x;
  // GEMM1: B[k][n] = W2[n][k], K=48 (3 k-tiles exactly), N=128
  for (int idx = tid; idx < 3 * 3 * 16 * 32; idx += 256) {
    int lane = idx & 31;
    int nt = (idx >> 5) & 15;
    int kt = (idx >> 9) % 3;
    int s  = idx / (32 * 16 * 3);
    int q = lane & 3, g = lane >> 2;
    int n = nt * 8 + g;
    int k0 = kt * 16 + 2 * q;
    uint32_t lo = (uint32_t)splitbits(w2[n * 48 + k0], s)
                | ((uint32_t)splitbits(w2[n * 48 + k0 + 1], s) << 16);
    uint32_t hi = (uint32_t)splitbits(w2[n * 48 + k0 + 8], s)
                | ((uint32_t)splitbits(w2[n * 48 + k0 + 9], s) << 16);
    g_w2frag[idx] = (u64)lo | ((u64)hi << 32);
  }
  // GEMM2: B[k][n] = W3[n][k], K=128 (8 k-chunks), N=16
  for (int idx = tid; idx < 3 * 8 * 2 * 32; idx += 256) {
    int lane = idx & 31;
    int nt = (idx >> 5) & 1;
    int kc = (idx >> 6) & 7;
    int s  = idx / (32 * 2 * 8);
    int q = lane & 3, g = lane >> 2;
    int n = nt * 8 + g;
    int k0 = kc * 16 + 2 * q;
    uint32_t lo = (uint32_t)splitbits(w3[n * 128 + k0], s)
                | ((uint32_t)splitbits(w3[n * 128 + k0 + 1], s) << 16);
    uint32_t hi = (uint32_t)splitbits(w3[n * 128 + k0 + 8], s)
                | ((uint32_t)splitbits(w3[n * 128 + k0 + 9], s) << 16);
    g_w3frag[idx] = (u64)lo | ((u64)hi << 32);
  }
}

// ---------------------------------------------------------------------------
// stepT: fused CA step via warp-MMA. 256 threads, 128-px tile (8 rows x 16).
// Warp w owns image-tile row w (A-tile rows = pixels 16w..16w+15).
// ---------------------------------------------------------------------------
#define SM_W2F 0
#define SM_W3F 36864
#define SM_YS  49152                       // bf16 Ys[3][128][52] (52 = padded 48)
#define SM_XS  (SM_YS + 3 * 128 * 52 * 2)  // 89088; [16][10][18] f32
#define SM_MIDA (SM_XS + 11520)            // 100608; [12][20]
#define SM_PREB (SM_MIDA + 960)            // 101568; [10][18]
#define SM_GA   (SM_PREB + 720)            // 102288; [10][18]
#define SMEM_TOTAL (SM_GA + 720)           // 103008

#define YROW 52

extern "C" __global__ void __launch_bounds__(256)
stepT(const float* __restrict__ x0in,
      float* __restrict__ frame_prev, int t, uint32_t k0, uint32_t k1)
{
  extern __shared__ char smem[];
  u64* w2f = (u64*)(smem + SM_W2F);
  u64* w3f = (u64*)(smem + SM_W3F);
  uint16_t* ys = (uint16_t*)(smem + SM_YS);
  float* xs   = (float*)(smem + SM_XS);     // [16][10][18]
  float* midA = (float*)(smem + SM_MIDA);
  float* preb = (float*)(smem + SM_PREB);
  float* ga   = (float*)(smem + SM_GA);

  const int tid = threadIdx.x;
  const int wid = tid >> 5;
  const int lane = tid & 31;
  const int b  = blockIdx.z;
  const int bh = blockIdx.y * 8;
  const int bw = blockIdx.x * 16;
  const int wb = t & 1, rb = 1 - wb;

  // ---- copy fragment weights (L2-resident after first tile) ----
  {
    const float4* s2 = (const float4*)g_w2frag;
    float4* d2 = (float4*)(smem + SM_W2F);
#pragma unroll
    for (int i = 0; i < 9; i++) d2[tid + i * 256] = s2[tid + i * 256];   // 2304
    const float4* s3 = (const float4*)g_w3frag;
    float4* d3 = (float4*)(smem + SM_W3F);
#pragma unroll
    for (int i = 0; i < 3; i++) d3[tid + i * 256] = s3[tid + i * 256];   // 768
  }

  // ---- halos for gating ----
  if (t > 0) {
    const float* aplane = g_mid[rb] + ((size_t)b * SDIM + 3) * PLANE;
    for (int i = tid; i < 240; i += 256) {
      int rr = i / 20, qq = i - rr * 20;
      int gh = bh - 2 + rr, gw = bw - 2 + qq;
      midA[i] = ((unsigned)gh < HH && (unsigned)gw < WW) ? aplane[gh * WW + gw] : -1e30f;
    }
    const float* prer = g_pre[rb] + (size_t)b * PLANE;
    for (int i = tid; i < 180; i += 256) {
      int rr = i / 18, qq = i - rr * 18;
      int gh = bh - 1 + rr, gw = bw - 1 + qq;
      preb[i] = ((unsigned)gh < HH && (unsigned)gw < WW) ? prer[gh * WW + gw] : 0.f;
    }
  }
  __syncthreads();

  if (t > 0) {
    for (int i = tid; i < 180; i += 256) {
      int rr = i / 18, qq = i - rr * 18;
      float m = -1e30f;
#pragma unroll
      for (int dr = 0; dr < 3; dr++)
#pragma unroll
        for (int dq = 0; dq < 3; dq++)
          m = fmaxf(m, midA[(rr + dr) * 20 + qq + dq]);
      ga[i] = (preb[i] != 0.f && m > 0.1f) ? 1.f : 0.f;
    }
  }
  __syncthreads();

  // ---- build gated x tile; emit frame t-1; liveness ----
  const float* srcb = (t == 0) ? (x0in + (size_t)b * SDIM * PLANE)
                               : (g_mid[rb] + (size_t)b * SDIM * PLANE);
  uint32_t nz = 0;
  for (int i = tid; i < 2880; i += 256) {
    int ch = i / 180;
    int rem = i - ch * 180;
    int rr = rem / 18, qq = rem - rr * 18;
    int gh = bh - 1 + rr, gw = bw - 1 + qq;
    float v = 0.f;
    if ((unsigned)gh < HH && (unsigned)gw < WW) {
      size_t gi = (size_t)ch * PLANE + gh * WW + gw;
      v = srcb[gi];
      if (t > 0) {
        v *= ga[rem];
        if ((unsigned)(rr - 1) < 8u && (unsigned)(qq - 1) < 16u)
          frame_prev[(size_t)b * SDIM * PLANE + gi] = v;
      }
    }
    nz |= (__float_as_uint(v) & 0x7fffffffu);
    xs[i] = v;
  }
  int tile_alive = __syncthreads_or(nz != 0u);

  float* midw = g_mid[wb] + (size_t)b * SDIM * PLANE;

  // ---- alive_pre for this step ----
  if (tid < 128) {
    int tp = tid, row = tp >> 4, col = tp & 15;
    const float* pa = xs + 3 * 180;
    float m = -1e30f;
#pragma unroll
    for (int dr = 0; dr < 3; dr++)
#pragma unroll
      for (int dq = 0; dq < 3; dq++)
        m = fmaxf(m, pa[(row + dr) * 18 + col + dq]);
    uint32_t pix = (uint32_t)((bh + row) * WW + (bw + col));
    g_pre[wb][(size_t)b * PLANE + pix] = (m > 0.1f) ? 1.f : 0.f;
  }

  if (!tile_alive) {
    // all-zero tile -> update == 0 exactly -> mid = 0
    if (tid < 128) {
      int row = tid >> 4, col = tid & 15;
      uint32_t pix = (uint32_t)((bh + row) * WW + (bw + col));
#pragma unroll
      for (int ch = 0; ch < 16; ch++) midw[(size_t)ch * PLANE + pix] = 0.f;
    }
    return;
  }

  // ---- perception -> Ys (bf16x3), 2 threads per pixel ----
  {
    int tp = tid >> 1, half = tid & 1;
    int row = tp >> 4, col = tp & 15;
    float yv[24];
#pragma unroll
    for (int j = 0; j < 8; j++) {
      int ch = half * 8 + j;
      const float* p = xs + ch * 180 + row * 18 + col;
      float a00 = p[0],  a01 = p[1],  a02 = p[2];
      float a10 = p[18], a11 = p[19], a12 = p[20];
      float a20 = p[36], a21 = p[37], a22 = p[38];
      yv[3 * j]     = a11;
      yv[3 * j + 1] = ((a02 - a00) + 2.f * (a12 - a10) + (a22 - a20)) * 0.125f;
      yv[3 * j + 2] = ((a20 - a00) + 2.f * (a21 - a01) + (a22 - a02)) * 0.125f;
    }
#pragma unroll
    for (int pr = 0; pr < 12; pr++) {
      uint16_t h0, m0, l0, h1, m1, l1;
      split3(yv[2 * pr], h0, m0, l0);
      split3(yv[2 * pr + 1], h1, m1, l1);
      int kk = half * 24 + 2 * pr;
      *(uint32_t*)&ys[(0 * 128 + tp) * YROW + kk] = (uint32_t)h0 | ((uint32_t)h1 << 16);
      *(uint32_t*)&ys[(1 * 128 + tp) * YROW + kk] = (uint32_t)m0 | ((uint32_t)m1 << 16);
      *(uint32_t*)&ys[(2 * 128 + tp) * YROW + kk] = (uint32_t)l0 | ((uint32_t)l1 << 16);
    }
  }
  __syncthreads();

  // ---- per-lane geometry ----
  const int q = lane & 3, g = lane >> 2;
  const int tp0 = 16 * wid + g;          // A-tile rows g / g+8 -> pixels tp0 / tp0+8
  const int colA = g, colB = g + 8;      // image cols (tile row == wid)
  const uint32_t pixA = (uint32_t)((bh + wid) * WW + (bw + colA));
  const uint32_t pixB = (uint32_t)((bh + wid) * WW + (bw + colB));

  // ---- RNG: 8 bits (4 channels x 2 pixels) ----
  uint32_t mask = 0;
  {
    const uint32_t base = (uint32_t)b * SDIM * PLANE;
    const int chs[4] = {2 * q, 2 * q + 1, 8 + 2 * q, 9 + 2 * q};
#pragma unroll
    for (int j = 0; j < 4; j++) {
      uint32_t o0, o1;
      threefry2x32(k0, k1, 0u, base + (uint32_t)chs[j] * PLANE + pixA, o0, o1);
      if (((o0 ^ o1) >> 9) > 0x400000u) mask |= (1u << j);
      threefry2x32(k0, k1, 0u, base + (uint32_t)chs[j] * PLANE + pixB, o0, o1);
      if (((o0 ^ o1) >> 9) > 0x400000u) mask |= (1u << (4 + j));
    }
  }

  // ---- A1 fragments (Y, 3 splits x 3 k-tiles) ----
  uint32_t a1f[3][3][4];
#pragma unroll
  for (int s = 0; s < 3; s++)
#pragma unroll
    for (int kt = 0; kt < 3; kt++) {
      const uint16_t* b0 = ys + (s * 128 + tp0) * YROW + kt * 16 + 2 * q;
      const uint16_t* b1 = ys + (s * 128 + tp0 + 8) * YROW + kt * 16 + 2 * q;
      a1f[s][kt][0] = *(const uint32_t*)b0;
      a1f[s][kt][1] = *(const uint32_t*)b1;
      a1f[s][kt][2] = *(const uint32_t*)(b0 + 8);
      a1f[s][kt][3] = *(const uint32_t*)(b1 + 8);
    }

  // ---- fused GEMM1 -> relu/split -> GEMM2, chunked over 16 hidden cols ----
  const int pa6[6] = {0, 0, 1, 1, 0, 2};
  const int pb6[6] = {0, 1, 0, 1, 2, 0};
  float d2a[2][4];
#pragma unroll
  for (int j = 0; j < 4; j++) { d2a[0][j] = 0.f; d2a[1][j] = 0.f; }

#pragma unroll 1
  for (int kc = 0; kc < 8; kc++) {
    float c1[2][4];
#pragma unroll
    for (int j = 0; j < 4; j++) { c1[0][j] = 0.f; c1[1][j] = 0.f; }

#pragma unroll
    for (int p = 0; p < 6; p++)
#pragma unroll
      for (int kt = 0; kt < 3; kt++) {
        const uint32_t* a = a1f[pa6[p]][kt];
#pragma unroll
        for (int nt = 0; nt < 2; nt++) {
          u64 bb = w2f[(((pb6[p] * 3 + kt) * 16) + kc * 2 + nt) * 32 + lane];
          mma_bf16(c1[nt], a, (uint32_t)bb, (uint32_t)(bb >> 32));
        }
      }

    // relu + bf16x3 split, C->A fragment identity (in registers)
    uint32_t a2[3][4];
#pragma unroll
    for (int nt = 0; nt < 2; nt++)
#pragma unroll
      for (int jj = 0; jj < 2; jj++) {
        float v0 = fmaxf(c1[nt][jj * 2], 0.f);
        float v1 = fmaxf(c1[nt][jj * 2 + 1], 0.f);
        uint16_t h0, m0, l0, h1, m1, l1;
        split3(v0, h0, m0, l0);
        split3(v1, h1, m1, l1);
        int ri = nt * 2 + jj;              // a0..a3
        a2[0][ri] = (uint32_t)h0 | ((uint32_t)h1 << 16);
        a2[1][ri] = (uint32_t)m0 | ((uint32_t)m1 << 16);
        a2[2][ri] = (uint32_t)l0 | ((uint32_t)l1 << 16);
      }

#pragma unroll
    for (int p = 0; p < 6; p++)
#pragma unroll
      for (int nt = 0; nt < 2; nt++) {
        u64 bb = w3f[(((pb6[p] * 8 + kc) * 2) + nt) * 32 + lane];
        mma_bf16(d2a[nt], a2[pa6[p]], (uint32_t)bb, (uint32_t)(bb >> 32));
      }
  }

  // ---- stochastic update, write mid from D2 fragments ----
#pragma unroll
  for (int nt = 0; nt < 2; nt++)
#pragma unroll
    for (int j = 0; j < 4; j++) {
      int ch = nt * 8 + 2 * q + (j & 1);
      int colp = (j >= 2) ? colB : colA;
      uint32_t pix = (j >= 2) ? pixB : pixA;
      float xv = xs[ch * 180 + (wid + 1) * 18 + (colp + 1)];
      uint32_t bit = (mask >> (((j >= 2) ? 4 : 0) + nt * 2 + (j & 1))) & 1u;
      midw[(size_t)ch * PLANE + pix] = xv + (bit ? d2a[nt][j] : 0.f);
    }
}

// ---------------------------------------------------------------------------
// stepC: gate and emit the final frame.
// ---------------------------------------------------------------------------
extern "C" __global__ void __launch_bounds__(256)
stepC(float* __restrict__ outf, int pb)
{
  int p = blockIdx.x * 256 + threadIdx.x;
  if (p >= NB * PLANE) return;
  int b = p / PLANE;
  int hw = p - b * PLANE;
  int h = hw / WW, w = hw - h * WW;

  const float* mida = g_mid[pb] + ((size_t)b * SDIM + 3) * PLANE;
  float m = -1e30f;
#pragma unroll
  for (int di = -1; di <= 1; di++) {
    int hh = h + di;
    if ((unsigned)hh >= HH) continue;
#pragma unroll
    for (int dj = -1; dj <= 1; dj++) {
      int wq = w + dj;
      if ((unsigned)wq >= WW) continue;
      m = fmaxf(m, mida[hh * WW + wq]);
    }
  }
  float gate = (g_pre[pb][p] != 0.f && m > 0.1f) ? 1.f : 0.f;

  size_t base = (size_t)b * SDIM * PLANE + (size_t)hw;
#pragma unroll
  for (int c = 0; c < 16; c++)
    outf[base + c * PLANE] = g_mid[pb][base + c * PLANE] * gate;
}

// ---------------------------------------------------------------------------
// kernel_launch
// ---------------------------------------------------------------------------
extern "C" void kernel_launch(void* const* d_in, const int* in_sizes, int n_in,
                              void* d_out, int out_size)
{
  const float* x0 = (const float*)d_in[0];
  const float* w2 = (const float*)d_in[3];
  const float* w3 = (const float*)d_in[4];
  float* out = (float*)d_out;

  const int nsteps = out_size / FRAME;

  cudaFuncSetAttribute(stepT, cudaFuncAttributeMaxDynamicSharedMemorySize, SMEM_TOTAL);

  prep<<<1, 256>>>(w2, w3);
  for (int t = 0; t < nsteps; t++) {
    uint32_t sk0, sk1;
    threefry2x32(0u, 42u, 0u, (uint32_t)t, sk0, sk1);
    float* fprev = out + (size_t)(t > 0 ? t - 1 : 0) * FRAME;
    stepT<<<dim3(6, 12, NB), 256, SMEM_TOTAL>>>(x0, fprev, t, sk0, sk1);
  }
  stepC<<<(NB * PLANE + 255) / 256, 256>>>(out + (size_t)(nsteps - 1) * FRAME,
                                           (nsteps - 1) & 1);
}